// round 1
// baseline (speedup 1.0000x reference)
#include <cuda_runtime.h>

#define NB 32
#define C 128
#define H 56
#define W 56
#define HW 3136
#define K3 384          // C*3
#define NSPLIT 4
#define KB_TOTAL 196    // HW/16
#define KB_PER (KB_TOTAL/NSPLIT)   // 49

// Scratch (device globals: no allocations allowed)
__device__ float g_t6[NB * C * HW];            // x + roll(x)          ~51 MB
__device__ float g_t8[NB * 4 * HW];            // conv(p5w*roll(x))    ~1.6 MB
__device__ float g_t7p[NSPLIT * NB * C * K3];  // t7^T partials        ~25 MB

// ---------------------------------------------------------------------------
// prep: t6[n,c,p] = x[n,c,p] + x[n,c,roll(p)]
//       t8[n,j,p] = sum_c conv_w[j,c]*p5w[c]*x[n,c,roll(p)]
// ---------------------------------------------------------------------------
__global__ void __launch_bounds__(256) prep_kernel(const float* __restrict__ x,
                                                   const float* __restrict__ p5w,
                                                   const float* __restrict__ conv_w) {
    int n = blockIdx.y;
    int p = blockIdx.x * 256 + threadIdx.x;
    if (p >= HW) return;
    int h = p / W;
    int w = p - h * W;
    int rp = ((h + H - 1) % H) * W + w;   // roll(+1) source index

    const float* xb = x + (size_t)n * C * HW;
    float* t6b = g_t6 + (size_t)n * C * HW;

    float a0 = 0.f, a1 = 0.f, a2 = 0.f, a3 = 0.f;
    #pragma unroll 4
    for (int c = 0; c < C; c++) {
        float xr = xb[c * HW + rp];
        float xp = xb[c * HW + p];
        t6b[c * HW + p] = xp + xr;
        float t = __ldg(&p5w[c]) * xr;
        a0 = fmaf(__ldg(&conv_w[c]),        t, a0);
        a1 = fmaf(__ldg(&conv_w[128 + c]),  t, a1);
        a2 = fmaf(__ldg(&conv_w[256 + c]),  t, a2);
        a3 = fmaf(__ldg(&conv_w[384 + c]),  t, a3);
    }
    float* t8b = g_t8 + (size_t)n * 4 * HW;
    t8b[p]          = a0;
    t8b[HW + p]     = a1;
    t8b[2 * HW + p] = a2;
    t8b[3 * HW + p] = a3;
}

// ---------------------------------------------------------------------------
// gemm1: t7t[s,n,c',m] = (1/(56*sqrt(384))) * sum_{p in split s} A[m,p]*t6[c',p]
//   A[m,p] = p2w[m,p] * x[c, h+2k-2, w]   (m = c*3+k, zero outside h bounds)
// Tile: 128(M) x 128(N), K-chunk 16, 8x8 per-thread micro-tile, K-split x4.
// ---------------------------------------------------------------------------
__global__ void __launch_bounds__(256) gemm1_kernel(const float* __restrict__ x,
                                                    const float* __restrict__ p2w) {
    __shared__ __align__(16) float As[16][132];
    __shared__ __align__(16) float Bs[16][132];

    int n  = blockIdx.y;
    int m0 = blockIdx.x * 128;
    int s  = blockIdx.z;

    int tid = threadIdx.x;
    int tx = tid & 15, ty = tid >> 4;
    int lc = tid & 15;   // kk within chunk (p offset)
    int lr = tid >> 4;   // base row for staging

    const float* xb  = x    + (size_t)n * C * HW;
    const float* t6b = g_t6 + (size_t)n * C * HW;

    float acc[8][8] = {};

    int kb_beg = s * KB_PER, kb_end = kb_beg + KB_PER;
    for (int kb = kb_beg; kb < kb_end; kb++) {
        int p0 = kb * 16;
        int p  = p0 + lc;
        int h  = p / 56;

        // stage A: As[kk][m] built on the fly (h-shift = whole-row offset)
        #pragma unroll
        for (int ps = 0; ps < 8; ps++) {
            int r = lr + ps * 16;
            int m = m0 + r;
            int c = m / 3;
            int k = m - c * 3;
            int hh = h + 2 * k - 2;
            float v = 0.f;
            if (hh >= 0 && hh < 56)
                v = p2w[(size_t)m * HW + p] * xb[c * HW + p + (2 * k - 2) * 56];
            As[lc][r] = v;
        }
        // stage B: Bs[kk][c'] = t6[c', p0+kk]
        #pragma unroll
        for (int ps = 0; ps < 8; ps++) {
            int nn = lr + ps * 16;
            Bs[lc][nn] = t6b[nn * HW + p0 + lc];
        }
        __syncthreads();

        #pragma unroll
        for (int kk = 0; kk < 16; kk++) {
            float a[8], b[8];
            *(float4*)&a[0] = *(const float4*)&As[kk][ty * 8];
            *(float4*)&a[4] = *(const float4*)&As[kk][ty * 8 + 4];
            *(float4*)&b[0] = *(const float4*)&Bs[kk][tx * 8];
            *(float4*)&b[4] = *(const float4*)&Bs[kk][tx * 8 + 4];
            #pragma unroll
            for (int i = 0; i < 8; i++)
                #pragma unroll
                for (int j = 0; j < 8; j++)
                    acc[i][j] = fmaf(a[i], b[j], acc[i][j]);
        }
        __syncthreads();
    }

    const float SC = 1.0f / (56.0f * 19.595917942265423f);  // 1/(sqrt(HW)*sqrt(3C))
    float* ob = g_t7p + ((size_t)(s * NB + n)) * C * K3;
    #pragma unroll
    for (int i = 0; i < 8; i++)
        #pragma unroll
        for (int j = 0; j < 8; j++)
            ob[(tx * 8 + j) * K3 + (m0 + ty * 8 + i)] = acc[i][j] * SC;
}

// ---------------------------------------------------------------------------
// gemm2: out[c,p] = sum_K t7t[c,K]*B2[K,p] + x[c,p]*t8[c&3,p]
//   B2[K=c'*3+k, p] = x[c', h, w+2k-2]  (zero outside w bounds)
// Tile: 128(M=c) x 128(N=p), K=384 in chunks of 16. Sums 4 t7 partials on A-load.
// ---------------------------------------------------------------------------
__global__ void __launch_bounds__(256) gemm2_kernel(const float* __restrict__ x,
                                                    float* __restrict__ out) {
    __shared__ __align__(16) float As[16][132];
    __shared__ __align__(16) float Bs[16][132];

    int n  = blockIdx.y;
    int p0 = blockIdx.x * 128;

    int tid = threadIdx.x;
    int tx = tid & 15, ty = tid >> 4;

    const float* xb = x     + (size_t)n * C * HW;
    const float* a2 = g_t7p + (size_t)n * C * K3;  // split 0 base
    const size_t SPL = (size_t)NB * C * K3;

    float acc[8][8] = {};

    int bcol = tid & 127;
    int bkr  = tid >> 7;               // 0 or 1
    int pcol = p0 + bcol;
    bool pok = pcol < HW;
    int wc = pok ? (pcol - (pcol / 56) * 56) : 0;

    for (int kb = 0; kb < 24; kb++) {
        int K0 = kb * 16;
        // stage A: sum the 4 K-split partials of t7^T
        #pragma unroll
        for (int ps = 0; ps < 8; ps++) {
            int c = (tid >> 4) + ps * 16;
            size_t idx = (size_t)c * K3 + K0 + (tid & 15);
            float v = a2[idx] + a2[idx + SPL] + a2[idx + 2 * SPL] + a2[idx + 3 * SPL];
            As[tid & 15][c] = v;
        }
        // stage B: unfold_w of x, on the fly
        #pragma unroll
        for (int ps = 0; ps < 8; ps++) {
            int kkr = bkr + 2 * ps;
            int K = K0 + kkr;
            int cp = K / 3;
            int k  = K - cp * 3;
            int sh = 2 * k - 2;
            float v = 0.f;
            if (pok) {
                int ww = wc + sh;
                if (ww >= 0 && ww < 56)
                    v = xb[cp * HW + pcol + sh];
            }
            Bs[kkr][bcol] = v;
        }
        __syncthreads();

        #pragma unroll
        for (int kk = 0; kk < 16; kk++) {
            float a[8], b[8];
            *(float4*)&a[0] = *(const float4*)&As[kk][ty * 8];
            *(float4*)&a[4] = *(const float4*)&As[kk][ty * 8 + 4];
            *(float4*)&b[0] = *(const float4*)&Bs[kk][tx * 8];
            *(float4*)&b[4] = *(const float4*)&Bs[kk][tx * 8 + 4];
            #pragma unroll
            for (int i = 0; i < 8; i++)
                #pragma unroll
                for (int j = 0; j < 8; j++)
                    acc[i][j] = fmaf(a[i], b[j], acc[i][j]);
        }
        __syncthreads();
    }

    const float* t8b = g_t8 + (size_t)n * 4 * HW;
    #pragma unroll
    for (int i = 0; i < 8; i++) {
        int c = ty * 8 + i;
        #pragma unroll
        for (int j = 0; j < 8; j++) {
            int p = p0 + tx * 8 + j;
            if (p < HW) {
                float t9 = xb[c * HW + p] * t8b[(c & 3) * HW + p];
                out[((size_t)n * C + c) * HW + p] = acc[i][j] + t9;
            }
        }
    }
}

// ---------------------------------------------------------------------------
extern "C" void kernel_launch(void* const* d_in, const int* in_sizes, int n_in,
                              void* d_out, int out_size) {
    const float* x      = (const float*)d_in[0];
    const float* p2w    = (const float*)d_in[1];
    const float* p5w    = (const float*)d_in[2];
    const float* conv_w = (const float*)d_in[3];
    float* out = (float*)d_out;

    prep_kernel<<<dim3((HW + 255) / 256, NB), 256>>>(x, p5w, conv_w);
    gemm1_kernel<<<dim3(3, NB, NSPLIT), 256>>>(x, p2w);
    gemm2_kernel<<<dim3((HW + 127) / 128, NB), 256>>>(x, out);
}

// round 3
// speedup vs baseline: 2.1338x; 2.1338x over previous
#include <cuda_runtime.h>
#include <cuda_bf16.h>
#include <cstdint>

#define NB 32
#define C 128
#define HW 3136
#define K3 384
#define NSPLIT 3

// tile: 128 rows x 192 bf16 (K tripled), row stride 400 bytes (pad for bank spread)
#define RSTRIDE 400
#define TILE_B (128 * RSTRIDE)            // 51200
#define SMEM_BYTES (2 * TILE_B + 1024)    // A + B + align slack

__device__ float g_t8[NB * 4 * HW];                  // conv(p5w * roll(x))
__device__ float g_t7p[NSPLIT * NB * C * K3];        // t7^T partials (scaled)

// ---------------- helpers ----------------
__device__ __forceinline__ uint32_t smem_u32(const void* p) {
    uint32_t a;
    asm("{ .reg .u64 t; cvta.to.shared.u64 t, %1; cvt.u32.u64 %0, t; }" : "=r"(a) : "l"(p));
    return a;
}

__device__ __forceinline__ void ldsm4(uint32_t addr, uint32_t& r0, uint32_t& r1,
                                      uint32_t& r2, uint32_t& r3) {
    asm volatile("ldmatrix.sync.aligned.m8n8.x4.shared.b16 {%0,%1,%2,%3}, [%4];"
                 : "=r"(r0), "=r"(r1), "=r"(r2), "=r"(r3) : "r"(addr));
}

__device__ __forceinline__ void mma16816(float* c, uint32_t a0, uint32_t a1, uint32_t a2,
                                         uint32_t a3, uint32_t b0, uint32_t b1) {
    asm volatile(
        "mma.sync.aligned.m16n8k16.row.col.f32.bf16.bf16.f32 "
        "{%0,%1,%2,%3}, {%4,%5,%6,%7}, {%8,%9}, {%0,%1,%2,%3};"
        : "+f"(c[0]), "+f"(c[1]), "+f"(c[2]), "+f"(c[3])
        : "r"(a0), "r"(a1), "r"(a2), "r"(a3), "r"(b0), "r"(b1));
}

// split v[4] into bf16 hi/lo packed pairs
__device__ __forceinline__ void split4(const float v[4], uint2& hi, uint2& lo) {
    __nv_bfloat16 h0 = __float2bfloat16(v[0]), h1 = __float2bfloat16(v[1]);
    __nv_bfloat16 h2 = __float2bfloat16(v[2]), h3 = __float2bfloat16(v[3]);
    __nv_bfloat16 l0 = __float2bfloat16(v[0] - __bfloat162float(h0));
    __nv_bfloat16 l1 = __float2bfloat16(v[1] - __bfloat162float(h1));
    __nv_bfloat16 l2 = __float2bfloat16(v[2] - __bfloat162float(h2));
    __nv_bfloat16 l3 = __float2bfloat16(v[3] - __bfloat162float(h3));
    hi.x = (uint32_t)__bfloat16_as_ushort(h0) | ((uint32_t)__bfloat16_as_ushort(h1) << 16);
    hi.y = (uint32_t)__bfloat16_as_ushort(h2) | ((uint32_t)__bfloat16_as_ushort(h3) << 16);
    lo.x = (uint32_t)__bfloat16_as_ushort(l0) | ((uint32_t)__bfloat16_as_ushort(l1) << 16);
    lo.y = (uint32_t)__bfloat16_as_ushort(l2) | ((uint32_t)__bfloat16_as_ushort(l3) << 16);
}

// A' blocks: [hi | lo | hi]   B' blocks: [hi | hi | lo]   (64 cols = 128 bytes each)
__device__ __forceinline__ void store_tripA(char* base, const float v[4]) {
    uint2 hi, lo; split4(v, hi, lo);
    *(uint2*)(base)       = hi;
    *(uint2*)(base + 128) = lo;
    *(uint2*)(base + 256) = hi;
}
__device__ __forceinline__ void store_tripB(char* base, const float v[4]) {
    uint2 hi, lo; split4(v, hi, lo);
    *(uint2*)(base)       = hi;
    *(uint2*)(base + 128) = hi;
    *(uint2*)(base + 256) = lo;
}

// one chunk of MMAs: K = 192 bf16 = 12 k16 steps; warp tile 32(M) x 64(N)
__device__ __forceinline__ void mma_tile(uint32_t As, uint32_t Bs, int wr, int wc,
                                         int lane, float acc[2][8][4]) {
    const uint32_t a_row = (uint32_t)(wr * 32 + (lane & 15)) * RSTRIDE + ((lane >> 4) << 4);
    const int brow = (lane & 7) + ((lane & 16) >> 1);
    const uint32_t b_koff = (uint32_t)((lane & 8) << 1);
    #pragma unroll
    for (int ks = 0; ks < 12; ks++) {
        uint32_t kb = ks * 32;
        uint32_t a[2][4];
        #pragma unroll
        for (int mi = 0; mi < 2; mi++)
            ldsm4(As + a_row + (uint32_t)(mi * 16) * RSTRIDE + kb,
                  a[mi][0], a[mi][1], a[mi][2], a[mi][3]);
        uint32_t b[8][2];
        #pragma unroll
        for (int nq = 0; nq < 4; nq++) {
            uint32_t r0, r1, r2, r3;
            ldsm4(Bs + (uint32_t)(wc * 64 + nq * 16 + brow) * RSTRIDE + kb + b_koff,
                  r0, r1, r2, r3);
            b[nq * 2][0] = r0; b[nq * 2][1] = r1;
            b[nq * 2 + 1][0] = r2; b[nq * 2 + 1][1] = r3;
        }
        #pragma unroll
        for (int mi = 0; mi < 2; mi++)
            #pragma unroll
            for (int ni = 0; ni < 8; ni++)
                mma16816(acc[mi][ni], a[mi][0], a[mi][1], a[mi][2], a[mi][3],
                         b[ni][0], b[ni][1]);
    }
}

// ---------------------------------------------------------------------------
// prep: t8[n,j,p] = sum_c conv_w[j,c]*p5w[c]*x[n,c,roll_h(p)]
// ---------------------------------------------------------------------------
__global__ void __launch_bounds__(256) prep_kernel(const float* __restrict__ x,
                                                   const float* __restrict__ p5w,
                                                   const float* __restrict__ conv_w) {
    int n = blockIdx.y;
    int p = blockIdx.x * 256 + threadIdx.x;
    if (p >= HW) return;
    int rp = (p >= 56) ? (p - 56) : (p + 3080);

    const float* xb = x + (size_t)n * C * HW;
    float a0 = 0.f, a1 = 0.f, a2 = 0.f, a3 = 0.f;
    #pragma unroll 4
    for (int c = 0; c < C; c++) {
        float xr = xb[c * HW + rp];
        float t = __ldg(&p5w[c]) * xr;
        a0 = fmaf(__ldg(&conv_w[c]),       t, a0);
        a1 = fmaf(__ldg(&conv_w[128 + c]), t, a1);
        a2 = fmaf(__ldg(&conv_w[256 + c]), t, a2);
        a3 = fmaf(__ldg(&conv_w[384 + c]), t, a3);
    }
    float* t8b = g_t8 + (size_t)n * 4 * HW;
    t8b[p]          = a0;
    t8b[HW + p]     = a1;
    t8b[2 * HW + p] = a2;
    t8b[3 * HW + p] = a3;
}

// ---------------------------------------------------------------------------
// gemm1: t7T[s][n][c'][m] = SC * sum_{p in split} t6[c',p] * (p2w*unfold_h)[m,p]
// D rows = c' (M=128), cols = m (N=128 tile of 384). K chunk = 64 fp32 (192 bf16).
// grid: (3 m-tiles, 32 batches, 3 k-splits)
// ---------------------------------------------------------------------------
__global__ void __launch_bounds__(256, 2) gemm1_kernel(const float* __restrict__ x,
                                                       const float* __restrict__ p2w) {
    extern __shared__ char smem_raw[];
    char* smp = (char*)(((uintptr_t)smem_raw + 1023) & ~(uintptr_t)1023);
    char* Asp = smp;
    char* Bsp = smp + TILE_B;
    uint32_t As = smem_u32(Asp), Bs = smem_u32(Bsp);

    const int tid = threadIdx.x, lane = tid & 31, wid = tid >> 5;
    const int wr = wid >> 1, wc = wid & 1;
    const int n = blockIdx.y, m0 = blockIdx.x * 128, s = blockIdx.z;

    const float* xb = x + (size_t)n * C * HW;
    float acc[2][8][4] = {};

    const int beg[4] = {0, 17, 33, 49};
    const int pcq = (tid & 15) * 4;
    const int rw = tid >> 4;

    for (int kb = beg[s]; kb < beg[s + 1]; kb++) {
        int p0 = kb * 64;
        // stage A: t6 = x + roll(x), rows c'
        #pragma unroll
        for (int pass = 0; pass < 8; pass++) {
            int r = rw + pass * 16;
            const float* xr = xb + (size_t)r * HW;
            float v[4];
            #pragma unroll
            for (int i = 0; i < 4; i++) {
                int p = p0 + pcq + i;
                int rp = (p >= 56) ? (p - 56) : (p + 3080);
                v[i] = xr[p] + xr[rp];
            }
            store_tripA(Asp + r * RSTRIDE + pcq * 2, v);
        }
        // stage B: p2w * unfold_h(x), rows m
        #pragma unroll
        for (int pass = 0; pass < 8; pass++) {
            int mr = rw + pass * 16;
            int m = m0 + mr, c = m / 3, k = m - 3 * c, sh = 2 * k - 2;
            float4 w4 = *reinterpret_cast<const float4*>(p2w + (size_t)m * HW + p0 + pcq);
            const float* xr = xb + (size_t)c * HW;
            float v[4];
            #pragma unroll
            for (int i = 0; i < 4; i++) {
                int p = p0 + pcq + i;
                int hh = p / 56 + sh;
                v[i] = (hh >= 0 && hh < 56) ? (&w4.x)[i] * xr[p + sh * 56] : 0.f;
            }
            store_tripB(Bsp + mr * RSTRIDE + pcq * 2, v);
        }
        __syncthreads();
        mma_tile(As, Bs, wr, wc, lane, acc);
        __syncthreads();
    }

    // epilogue: scaled partial t7^T
    const float SC = 9.1126371e-4f;   // 1/(sqrt(3136)*sqrt(384))
    float* ob = g_t7p + ((size_t)(s * NB + n)) * C * K3;
    #pragma unroll
    for (int mi = 0; mi < 2; mi++) {
        #pragma unroll
        for (int ni = 0; ni < 8; ni++) {
            int row = wr * 32 + mi * 16 + (lane >> 2);
            int col = m0 + wc * 64 + ni * 8 + (lane & 3) * 2;
            float2 v0 = make_float2(acc[mi][ni][0] * SC, acc[mi][ni][1] * SC);
            float2 v1 = make_float2(acc[mi][ni][2] * SC, acc[mi][ni][3] * SC);
            *(float2*)(ob + (size_t)row * K3 + col)       = v0;
            *(float2*)(ob + (size_t)(row + 8) * K3 + col) = v1;
        }
    }
}

// ---------------------------------------------------------------------------
// gemm2: out[c,p] = sum_m t7T[c,m] * unfold_w(x)[m,p] + x[c,p]*t8[c&3,p]
// D rows = c (M=128), cols = p (N=128 tile). K = 384 in 6 chunks of 64.
// A = t7 (sum of 3 partials), B rows = p, cols = m.
// grid: (25 p-tiles, 32 batches)
// ---------------------------------------------------------------------------
__global__ void __launch_bounds__(256, 2) gemm2_kernel(const float* __restrict__ x,
                                                       float* __restrict__ out) {
    extern __shared__ char smem_raw[];
    char* smp = (char*)(((uintptr_t)smem_raw + 1023) & ~(uintptr_t)1023);
    char* Asp = smp;
    char* Bsp = smp + TILE_B;
    uint32_t As = smem_u32(Asp), Bs = smem_u32(Bsp);

    const int tid = threadIdx.x, lane = tid & 31, wid = tid >> 5;
    const int wr = wid >> 1, wc = wid & 1;
    const int n = blockIdx.y, p0 = blockIdx.x * 128;

    const float* xb = x + (size_t)n * C * HW;
    const float* t0p = g_t7p + ((size_t)(0 * NB + n)) * C * K3;
    const float* t1p = g_t7p + ((size_t)(1 * NB + n)) * C * K3;
    const float* t2p = g_t7p + ((size_t)(2 * NB + n)) * C * K3;

    float acc[2][8][4] = {};

    const int pcq = (tid & 15) * 4;
    const int rw = tid >> 4;
    // B staging map: row pl, half mq
    const int pl = tid >> 1;
    const int mq = (tid & 1) * 32;
    const int pg = p0 + pl;
    const bool pin = pg < HW;
    const int wcol = pg % 56;

    for (int ch = 0; ch < 6; ch++) {
        int m0c = ch * 64;
        // stage A: t7 = sum of 3 partials, rows c
        #pragma unroll
        for (int pass = 0; pass < 8; pass++) {
            int r = rw + pass * 16;
            size_t idx = (size_t)r * K3 + m0c + pcq;
            float4 v0 = *(const float4*)(t0p + idx);
            float4 v1 = *(const float4*)(t1p + idx);
            float4 v2 = *(const float4*)(t2p + idx);
            float v[4] = {v0.x + v1.x + v2.x, v0.y + v1.y + v2.y,
                          v0.z + v1.z + v2.z, v0.w + v1.w + v2.w};
            store_tripA(Asp + r * RSTRIDE + pcq * 2, v);
        }
        // stage B: unfold_w(x)^T, rows p(128), cols m(64); pack row-contiguous
        {
            uint32_t hi32[16], lo32[16];
            #pragma unroll
            for (int j = 0; j < 32; j++) {
                int m = m0c + mq + j, cp = m / 3, k = m - 3 * cp, sh = 2 * k - 2;
                float v = 0.f;
                if (pin) {
                    int ww = wcol + sh;
                    if (ww >= 0 && ww < 56) v = xb[(size_t)cp * HW + pg + sh];
                }
                __nv_bfloat16 h = __float2bfloat16(v);
                __nv_bfloat16 l = __float2bfloat16(v - __bfloat162float(h));
                uint32_t hb = (uint32_t)__bfloat16_as_ushort(h) << (16 * (j & 1));
                uint32_t lb = (uint32_t)__bfloat16_as_ushort(l) << (16 * (j & 1));
                if (j & 1) { hi32[j >> 1] |= hb; lo32[j >> 1] |= lb; }
                else       { hi32[j >> 1]  = hb; lo32[j >> 1]  = lb; }
            }
            char* bb = Bsp + pl * RSTRIDE + mq * 2;
            const uint4* h4 = (const uint4*)hi32;
            const uint4* l4 = (const uint4*)lo32;
            #pragma unroll
            for (int q = 0; q < 4; q++) {
                *(uint4*)(bb + q * 16)       = h4[q];
                *(uint4*)(bb + 128 + q * 16) = h4[q];
                *(uint4*)(bb + 256 + q * 16) = l4[q];
            }
        }
        __syncthreads();
        mma_tile(As, Bs, wr, wc, lane, acc);
        __syncthreads();
    }

    // epilogue: out = acc + x * t8[c%4]
    const float* t8b = g_t8 + (size_t)n * 4 * HW;
    float* outb = out + (size_t)n * C * HW;
    #pragma unroll
    for (int mi = 0; mi < 2; mi++) {
        #pragma unroll
        for (int ni = 0; ni < 8; ni++) {
            int c = wr * 32 + mi * 16 + (lane >> 2);
            int p = p0 + wc * 64 + ni * 8 + (lane & 3) * 2;
            if (p < HW) {
                #pragma unroll
                for (int h = 0; h < 2; h++) {
                    int cc = c + h * 8;
                    float2 xv  = *(const float2*)(xb  + (size_t)cc * HW + p);
                    float2 t8v = *(const float2*)(t8b + (size_t)(cc & 3) * HW + p);
                    float2 o = make_float2(acc[mi][ni][2 * h]     + xv.x * t8v.x,
                                           acc[mi][ni][2 * h + 1] + xv.y * t8v.y);
                    *(float2*)(outb + (size_t)cc * HW + p) = o;
                }
            }
        }
    }
}

// ---------------------------------------------------------------------------
extern "C" void kernel_launch(void* const* d_in, const int* in_sizes, int n_in,
                              void* d_out, int out_size) {
    const float* x      = (const float*)d_in[0];
    const float* p2w    = (const float*)d_in[1];
    const float* p5w    = (const float*)d_in[2];
    const float* conv_w = (const float*)d_in[3];
    float* out = (float*)d_out;

    cudaFuncSetAttribute(gemm1_kernel, cudaFuncAttributeMaxDynamicSharedMemorySize, SMEM_BYTES);
    cudaFuncSetAttribute(gemm2_kernel, cudaFuncAttributeMaxDynamicSharedMemorySize, SMEM_BYTES);

    prep_kernel<<<dim3((HW + 255) / 256, NB), 256>>>(x, p5w, conv_w);
    gemm1_kernel<<<dim3(3, NB, NSPLIT), 256, SMEM_BYTES>>>(x, p2w);
    gemm2_kernel<<<dim3(25, NB), 256, SMEM_BYTES>>>(x, out);
}

// round 4
// speedup vs baseline: 2.3073x; 1.0813x over previous
#include <cuda_runtime.h>
#include <cuda_bf16.h>
#include <cstdint>

#define NB 32
#define C 128
#define HW 3136
#define K3 384
#define NSPLIT 3

// tile: 128 rows x 64 bf16 cols ([hi 32 | lo 32]), stride 144 bytes
#define RS 144
#define TILE_B (128 * RS)                   // 18432
#define STAGE_B (2 * TILE_B)                // A + B = 36864
#define SMEM_BYTES (2 * STAGE_B + 1024)     // double buffer + align

__device__ float g_t8[NB * 4 * HW];
__device__ float g_t7p[NSPLIT * NB * C * K3];

// ---------------- helpers ----------------
__device__ __forceinline__ uint32_t smem_u32(const void* p) {
    uint32_t a;
    asm("{ .reg .u64 t; cvta.to.shared.u64 t, %1; cvt.u32.u64 %0, t; }" : "=r"(a) : "l"(p));
    return a;
}
__device__ __forceinline__ void ldsm4(uint32_t addr, uint32_t& r0, uint32_t& r1,
                                      uint32_t& r2, uint32_t& r3) {
    asm volatile("ldmatrix.sync.aligned.m8n8.x4.shared.b16 {%0,%1,%2,%3}, [%4];"
                 : "=r"(r0), "=r"(r1), "=r"(r2), "=r"(r3) : "r"(addr));
}
__device__ __forceinline__ void mma16816(float* c, uint32_t a0, uint32_t a1, uint32_t a2,
                                         uint32_t a3, uint32_t b0, uint32_t b1) {
    asm volatile(
        "mma.sync.aligned.m16n8k16.row.col.f32.bf16.bf16.f32 "
        "{%0,%1,%2,%3}, {%4,%5,%6,%7}, {%8,%9}, {%0,%1,%2,%3};"
        : "+f"(c[0]), "+f"(c[1]), "+f"(c[2]), "+f"(c[3])
        : "r"(a0), "r"(a1), "r"(a2), "r"(a3), "r"(b0), "r"(b1));
}
__device__ __forceinline__ void split4(const float v[4], uint2& hi, uint2& lo) {
    __nv_bfloat16 h0 = __float2bfloat16(v[0]), h1 = __float2bfloat16(v[1]);
    __nv_bfloat16 h2 = __float2bfloat16(v[2]), h3 = __float2bfloat16(v[3]);
    __nv_bfloat16 l0 = __float2bfloat16(v[0] - __bfloat162float(h0));
    __nv_bfloat16 l1 = __float2bfloat16(v[1] - __bfloat162float(h1));
    __nv_bfloat16 l2 = __float2bfloat16(v[2] - __bfloat162float(h2));
    __nv_bfloat16 l3 = __float2bfloat16(v[3] - __bfloat162float(h3));
    hi.x = (uint32_t)__bfloat16_as_ushort(h0) | ((uint32_t)__bfloat16_as_ushort(h1) << 16);
    hi.y = (uint32_t)__bfloat16_as_ushort(h2) | ((uint32_t)__bfloat16_as_ushort(h3) << 16);
    lo.x = (uint32_t)__bfloat16_as_ushort(l0) | ((uint32_t)__bfloat16_as_ushort(l1) << 16);
    lo.y = (uint32_t)__bfloat16_as_ushort(l2) | ((uint32_t)__bfloat16_as_ushort(l3) << 16);
}
// store [hi(32 cols=64B) | lo(32 cols=64B)] at row, col4 within the hi block
__device__ __forceinline__ void store_hl(char* base, int row, int col4, const float v[4]) {
    uint2 hi, lo; split4(v, hi, lo);
    char* p = base + row * RS + col4 * 2;
    *(uint2*)(p)      = hi;
    *(uint2*)(p + 64) = lo;
}

// MMA over one 32-fp32-K chunk: 3 product passes x 2 k16 steps
__device__ __forceinline__ void mma_tile32(uint32_t As, uint32_t Bs, int wr, int wc,
                                           int lane, float acc[2][8][4]) {
    const uint32_t a_row = (uint32_t)(wr * 32 + (lane & 15)) * RS + ((lane >> 4) << 4);
    const int brow = (lane & 7) + ((lane & 16) >> 1);
    const uint32_t b_k = (uint32_t)((lane & 8) << 1);
    const uint32_t aoff[3] = {0, 0, 64}, boff[3] = {0, 64, 0};
    #pragma unroll
    for (int pp = 0; pp < 3; pp++) {
        #pragma unroll
        for (int ks = 0; ks < 2; ks++) {
            uint32_t ka = aoff[pp] + ks * 32, kb = boff[pp] + ks * 32;
            uint32_t a[2][4];
            #pragma unroll
            for (int mi = 0; mi < 2; mi++)
                ldsm4(As + a_row + (uint32_t)(mi * 16) * RS + ka,
                      a[mi][0], a[mi][1], a[mi][2], a[mi][3]);
            uint32_t b[8][2];
            #pragma unroll
            for (int nq = 0; nq < 4; nq++) {
                uint32_t r0, r1, r2, r3;
                ldsm4(Bs + (uint32_t)(wc * 64 + nq * 16 + brow) * RS + kb + b_k,
                      r0, r1, r2, r3);
                b[nq * 2][0] = r0;     b[nq * 2][1] = r1;
                b[nq * 2 + 1][0] = r2; b[nq * 2 + 1][1] = r3;
            }
            #pragma unroll
            for (int mi = 0; mi < 2; mi++)
                #pragma unroll
                for (int ni = 0; ni < 8; ni++)
                    mma16816(acc[mi][ni], a[mi][0], a[mi][1], a[mi][2], a[mi][3],
                             b[ni][0], b[ni][1]);
        }
    }
}

// ---------------------------------------------------------------------------
// prep: t8[n,j,p] = sum_c conv_w[j,c]*p5w[c]*x[n,c,roll_h(p)]
// 4 threads per pixel over c-quarters, smem reduce. grid (49, 32) x 256
// ---------------------------------------------------------------------------
__global__ void __launch_bounds__(256) prep_kernel(const float* __restrict__ x,
                                                   const float* __restrict__ p5w,
                                                   const float* __restrict__ conv_w) {
    __shared__ float red[4][4][64];   // [q][j][pl]
    int n = blockIdx.y;
    int tid = threadIdx.x;
    int pl = tid & 63, q = tid >> 6;
    int p = blockIdx.x * 64 + pl;
    int rp = (p >= 56) ? (p - 56) : (p + 3080);

    const float* xb = x + (size_t)n * C * HW;
    float s0 = 0.f, s1 = 0.f, s2 = 0.f, s3 = 0.f;
    int c0 = q * 32;
    #pragma unroll 4
    for (int i = 0; i < 32; i++) {
        int c = c0 + i;
        float t = __ldg(&p5w[c]) * xb[(size_t)c * HW + rp];
        s0 = fmaf(__ldg(&conv_w[c]),       t, s0);
        s1 = fmaf(__ldg(&conv_w[128 + c]), t, s1);
        s2 = fmaf(__ldg(&conv_w[256 + c]), t, s2);
        s3 = fmaf(__ldg(&conv_w[384 + c]), t, s3);
    }
    red[q][0][pl] = s0; red[q][1][pl] = s1; red[q][2][pl] = s2; red[q][3][pl] = s3;
    __syncthreads();
    int j = tid >> 6;   // 0..3
    float r = red[0][j][pl] + red[1][j][pl] + red[2][j][pl] + red[3][j][pl];
    g_t8[((size_t)n * 4 + j) * HW + blockIdx.x * 64 + pl] = r;
}

// ---------------------------------------------------------------------------
// gemm1: t7T partials. D rows = c'(128), cols = m (128-tile of 384).
// K = 3136, chunk 32, 98 chunks over 3 splits. Double-buffered.
// ---------------------------------------------------------------------------
__device__ __forceinline__ void g1_stage(char* Asp, char* Bsp,
                                         const float* xb, const float* p2w,
                                         int m0, int p0, int tid) {
    int col4 = (tid & 7) * 4;
    int rbase = tid >> 3;
    // A: t6 = x + roll(x), rows c'
    #pragma unroll
    for (int pass = 0; pass < 4; pass++) {
        int r = rbase + pass * 32;
        const float* xr = xb + (size_t)r * HW;
        float v[4];
        #pragma unroll
        for (int i = 0; i < 4; i++) {
            int p = p0 + col4 + i;
            int rp = (p >= 56) ? (p - 56) : (p + 3080);
            v[i] = xr[p] + xr[rp];
        }
        store_hl(Asp, r, col4, v);
    }
    // B: p2w * unfold_h(x), rows m
    #pragma unroll
    for (int pass = 0; pass < 4; pass++) {
        int mr = rbase + pass * 32;
        int m = m0 + mr, c = m / 3, k = m - 3 * c, sh = 2 * k - 2;
        float4 w4 = *reinterpret_cast<const float4*>(p2w + (size_t)m * HW + p0 + col4);
        const float* xr = xb + (size_t)c * HW;
        float v[4];
        #pragma unroll
        for (int i = 0; i < 4; i++) {
            int p = p0 + col4 + i;
            int hh = p / 56 + sh;
            v[i] = (hh >= 0 && hh < 56) ? (&w4.x)[i] * xr[p + sh * 56] : 0.f;
        }
        store_hl(Bsp, mr, col4, v);
    }
}

__global__ void __launch_bounds__(256, 2) gemm1_kernel(const float* __restrict__ x,
                                                       const float* __restrict__ p2w) {
    extern __shared__ char smem_raw[];
    char* smp = (char*)(((uintptr_t)smem_raw + 1023) & ~(uintptr_t)1023);

    const int tid = threadIdx.x, lane = tid & 31, wid = tid >> 5;
    const int wr = wid >> 1, wc = wid & 1;
    const int n = blockIdx.y, m0 = blockIdx.x * 128, s = blockIdx.z;

    const float* xb = x + (size_t)n * C * HW;
    float acc[2][8][4] = {};

    const int beg[4] = {0, 33, 66, 98};
    const int nch = beg[s + 1] - beg[s];
    const int pbase = beg[s] * 32;

    // prologue: stage chunk 0 into buffer 0
    g1_stage(smp, smp + TILE_B, xb, p2w, m0, pbase, tid);
    __syncthreads();

    for (int ch = 0; ch < nch; ch++) {
        char* cur = smp + (ch & 1) * STAGE_B;
        mma_tile32(smem_u32(cur), smem_u32(cur + TILE_B), wr, wc, lane, acc);
        if (ch + 1 < nch) {
            char* nxt = smp + ((ch + 1) & 1) * STAGE_B;
            g1_stage(nxt, nxt + TILE_B, xb, p2w, m0, pbase + (ch + 1) * 32, tid);
        }
        __syncthreads();
    }

    const float SC = 9.1126371e-4f;   // 1/(sqrt(3136)*sqrt(384))
    float* ob = g_t7p + ((size_t)(s * NB + n)) * C * K3;
    #pragma unroll
    for (int mi = 0; mi < 2; mi++) {
        #pragma unroll
        for (int ni = 0; ni < 8; ni++) {
            int row = wr * 32 + mi * 16 + (lane >> 2);
            int col = m0 + wc * 64 + ni * 8 + (lane & 3) * 2;
            float2 v0 = make_float2(acc[mi][ni][0] * SC, acc[mi][ni][1] * SC);
            float2 v1 = make_float2(acc[mi][ni][2] * SC, acc[mi][ni][3] * SC);
            *(float2*)(ob + (size_t)row * K3 + col)       = v0;
            *(float2*)(ob + (size_t)(row + 8) * K3 + col) = v1;
        }
    }
}

// ---------------------------------------------------------------------------
// gemm2: out[c,p] = sum_m t7[c,m]*unfold_w(x)[m,p] + x[c,p]*t8[c&3,p]
// D rows = c(128), cols = p(128-tile). K = 384, 12 chunks of 32. Double-buffered.
// ---------------------------------------------------------------------------
__device__ __forceinline__ void g2_stage(char* Asp, char* Bsp, const float* xb,
                                         const float* t0p, const float* t1p,
                                         const float* t2p, int p0, int m0c, int tid) {
    int col4 = (tid & 7) * 4;
    int rbase = tid >> 3;
    // A: t7 = sum of 3 partials, rows c
    #pragma unroll
    for (int pass = 0; pass < 4; pass++) {
        int r = rbase + pass * 32;
        size_t idx = (size_t)r * K3 + m0c + col4;
        float4 v0 = *(const float4*)(t0p + idx);
        float4 v1 = *(const float4*)(t1p + idx);
        float4 v2 = *(const float4*)(t2p + idx);
        float v[4] = {v0.x + v1.x + v2.x, v0.y + v1.y + v2.y,
                      v0.z + v1.z + v2.z, v0.w + v1.w + v2.w};
        store_hl(Asp, r, col4, v);
    }
    // B: unfold_w(x)^T, rows p(128), 32 m-cols
    {
        int pl = tid >> 1;
        int mh = (tid & 1) * 16;
        int pg = p0 + pl;
        bool pin = pg < HW;
        int wcol = pin ? (pg % 56) : 0;
        uint32_t hi32[8], lo32[8];
        #pragma unroll
        for (int j = 0; j < 16; j++) {
            int m = m0c + mh + j, cp = m / 3, k = m - 3 * cp, sh = 2 * k - 2;
            float v = 0.f;
            if (pin) {
                int ww = wcol + sh;
                if (ww >= 0 && ww < 56) v = xb[(size_t)cp * HW + pg + sh];
            }
            __nv_bfloat16 h = __float2bfloat16(v);
            __nv_bfloat16 l = __float2bfloat16(v - __bfloat162float(h));
            uint32_t hb = (uint32_t)__bfloat16_as_ushort(h) << (16 * (j & 1));
            uint32_t lb = (uint32_t)__bfloat16_as_ushort(l) << (16 * (j & 1));
            if (j & 1) { hi32[j >> 1] |= hb; lo32[j >> 1] |= lb; }
            else       { hi32[j >> 1]  = hb; lo32[j >> 1]  = lb; }
        }
        char* bb = Bsp + pl * RS + mh * 2;
        *(uint4*)(bb)           = *(const uint4*)(hi32);
        *(uint4*)(bb + 16)      = *(const uint4*)(hi32 + 4);
        *(uint4*)(bb + 64)      = *(const uint4*)(lo32);
        *(uint4*)(bb + 64 + 16) = *(const uint4*)(lo32 + 4);
    }
}

__global__ void __launch_bounds__(256, 2) gemm2_kernel(const float* __restrict__ x,
                                                       float* __restrict__ out) {
    extern __shared__ char smem_raw[];
    char* smp = (char*)(((uintptr_t)smem_raw + 1023) & ~(uintptr_t)1023);

    const int tid = threadIdx.x, lane = tid & 31, wid = tid >> 5;
    const int wr = wid >> 1, wc = wid & 1;
    const int n = blockIdx.y, p0 = blockIdx.x * 128;

    const float* xb  = x + (size_t)n * C * HW;
    const float* t0p = g_t7p + ((size_t)(0 * NB + n)) * C * K3;
    const float* t1p = g_t7p + ((size_t)(1 * NB + n)) * C * K3;
    const float* t2p = g_t7p + ((size_t)(2 * NB + n)) * C * K3;

    float acc[2][8][4] = {};
    const int NCH = 12;

    g2_stage(smp, smp + TILE_B, xb, t0p, t1p, t2p, p0, 0, tid);
    __syncthreads();

    for (int ch = 0; ch < NCH; ch++) {
        char* cur = smp + (ch & 1) * STAGE_B;
        mma_tile32(smem_u32(cur), smem_u32(cur + TILE_B), wr, wc, lane, acc);
        if (ch + 1 < NCH) {
            char* nxt = smp + ((ch + 1) & 1) * STAGE_B;
            g2_stage(nxt, nxt + TILE_B, xb, t0p, t1p, t2p, p0, (ch + 1) * 32, tid);
        }
        __syncthreads();
    }

    // epilogue: out = acc + x * t8[c%4]
    const float* t8b = g_t8 + (size_t)n * 4 * HW;
    float* outb = out + (size_t)n * C * HW;
    #pragma unroll
    for (int mi = 0; mi < 2; mi++) {
        #pragma unroll
        for (int ni = 0; ni < 8; ni++) {
            int c = wr * 32 + mi * 16 + (lane >> 2);
            int p = p0 + wc * 64 + ni * 8 + (lane & 3) * 2;
            if (p < HW) {
                #pragma unroll
                for (int h = 0; h < 2; h++) {
                    int cc = c + h * 8;
                    float2 xv  = *(const float2*)(xb  + (size_t)cc * HW + p);
                    float2 t8v = *(const float2*)(t8b + (size_t)(cc & 3) * HW + p);
                    float2 o = make_float2(acc[mi][ni][2 * h]     + xv.x * t8v.x,
                                           acc[mi][ni][2 * h + 1] + xv.y * t8v.y);
                    *(float2*)(outb + (size_t)cc * HW + p) = o;
                }
            }
        }
    }
}

// ---------------------------------------------------------------------------
extern "C" void kernel_launch(void* const* d_in, const int* in_sizes, int n_in,
                              void* d_out, int out_size) {
    const float* x      = (const float*)d_in[0];
    const float* p2w    = (const float*)d_in[1];
    const float* p5w    = (const float*)d_in[2];
    const float* conv_w = (const float*)d_in[3];
    float* out = (float*)d_out;

    cudaFuncSetAttribute(gemm1_kernel, cudaFuncAttributeMaxDynamicSharedMemorySize, SMEM_BYTES);
    cudaFuncSetAttribute(gemm2_kernel, cudaFuncAttributeMaxDynamicSharedMemorySize, SMEM_BYTES);

    prep_kernel<<<dim3(49, NB), 256>>>(x, p5w, conv_w);
    gemm1_kernel<<<dim3(3, NB, NSPLIT), 256, SMEM_BYTES>>>(x, p2w);
    gemm2_kernel<<<dim3(25, NB), 256, SMEM_BYTES>>>(x, out);
}